// round 3
// baseline (speedup 1.0000x reference)
#include <cuda_runtime.h>
#include <math.h>

#define NMAX 4096
#define ONE_THIRD2 (2.0f / 3.0f)
#define FOUR_THIRDS (4.0f / 3.0f)

// Scratch (no allocations allowed)
__device__ float g_min_dist[NMAX];
__device__ float g_params[3];   // [0]=1/dil, [1]=dil^2, [2]=dil

// ---------------------------------------------------------------------------
// Kernel 1: per-node nearest-neighbor distance (sqrt of min d2 over j != i)
// 8 nodes per block, nodes staged in shared memory.
// ---------------------------------------------------------------------------
__global__ __launch_bounds__(256) void min_dist_kernel(const float2* __restrict__ nodes, int N) {
    __shared__ float2 s_nodes[NMAX];
    __shared__ float  s_red[8];
    const int tid = threadIdx.x;
    for (int i = tid; i < N; i += 256) s_nodes[i] = nodes[i];
    __syncthreads();

    const int i0 = blockIdx.x * 8;
    for (int ii = 0; ii < 8; ii++) {
        const int i = i0 + ii;
        if (i >= N) break;
        const float2 xi = s_nodes[i];
        float m = 3.4e38f;
        for (int j = tid; j < N; j += 256) {
            float dx = xi.x - s_nodes[j].x;
            float dy = xi.y - s_nodes[j].y;
            float d2 = fmaf(dy, dy, dx * dx);
            if (j != i) m = fminf(m, d2);
        }
        #pragma unroll
        for (int o = 16; o; o >>= 1) m = fminf(m, __shfl_xor_sync(0xffffffffu, m, o));
        if ((tid & 31) == 0) s_red[tid >> 5] = m;
        __syncthreads();
        if (tid == 0) {
            float mm = s_red[0];
            #pragma unroll
            for (int w = 1; w < 8; w++) mm = fminf(mm, s_red[w]);
            g_min_dist[i] = sqrtf(mm);
        }
        __syncthreads();
    }
}

// ---------------------------------------------------------------------------
// Kernel 2: dilation = 2.5 * mean(min_dist). Deterministic fp64 tree reduce.
// ---------------------------------------------------------------------------
__global__ __launch_bounds__(256) void dilation_kernel(int N) {
    __shared__ double s_sum[256];
    const int tid = threadIdx.x;
    double s = 0.0;
    for (int i = tid; i < N; i += 256) s += (double)g_min_dist[i];
    s_sum[tid] = s;
    __syncthreads();
    #pragma unroll
    for (int o = 128; o; o >>= 1) {
        if (tid < o) s_sum[tid] += s_sum[tid + o];
        __syncthreads();
    }
    if (tid == 0) {
        double dil = 2.5 * (s_sum[0] / (double)N);
        g_params[0] = (float)(1.0 / dil);
        g_params[1] = (float)(dil * dil);
        g_params[2] = (float)dil;
    }
}

// ---------------------------------------------------------------------------
// Cubic spline weight (matches reference piecewise formula + support mask)
// ---------------------------------------------------------------------------
__device__ __forceinline__ float cubic_w(float q) {
    float w;
    if (q <= 0.5f) w = ONE_THIRD2 + 4.f * q * q * (q - 1.f);
    else           w = FOUR_THIRDS + q * (-4.f + q * (4.f - FOUR_THIRDS * q));
    return (q <= 1.f) ? w : 0.f;
}

// ---------------------------------------------------------------------------
// Kernel 3: main RKPM. One block of 256 threads handles 4 query points.
// Pass 1: accumulate 6-entry symmetric moment matrix per query (registers),
//         warp-shuffle + smem reduce, 4 parallel fp64 3x3 adjugate inversions.
// Pass 2: recompute w per (b,n), write phi/phi_x/phi_y as coalesced float4.
// ---------------------------------------------------------------------------
__global__ __launch_bounds__(256) void rkpm_kernel(const float2* __restrict__ x,
                                                   const float2* __restrict__ nodes,
                                                   float* __restrict__ out,
                                                   int B, int N) {
    __shared__ float2 s_nodes[NMAX];
    __shared__ float  s_part[8][24];
    __shared__ float  s_minv[4][6];
    __shared__ float2 s_q[4];

    const int tid = threadIdx.x;
    for (int i = tid; i < N; i += 256) s_nodes[i] = nodes[i];
    const int b0 = blockIdx.x * 4;
    if (tid < 4) {
        int b = b0 + tid;
        s_q[tid] = (b < B) ? x[b] : make_float2(1e10f, 1e10f);
    }
    __syncthreads();

    const float inv_dil = g_params[0];
    const float dil2    = g_params[1];

    float2 qv[4];
    #pragma unroll
    for (int q = 0; q < 4; q++) qv[q] = s_q[q];

    float acc[4][6];
    #pragma unroll
    for (int q = 0; q < 4; q++)
        #pragma unroll
        for (int c = 0; c < 6; c++) acc[q][c] = 0.f;

    // ---- Pass 1: moment matrices ----
    for (int n = tid; n < N; n += 256) {
        const float2 nd = s_nodes[n];
        #pragma unroll
        for (int q = 0; q < 4; q++) {
            float dx = qv[q].x - nd.x;
            float dy = qv[q].y - nd.y;
            float d2 = dx * dx + dy * dy + 1e-10f;
            if (d2 <= dil2) {                      // skip sqrt/poly for ~99.5% of pairs
                float qq = sqrtf(d2) * inv_dil;
                float w = cubic_w(qq);
                acc[q][0] += w;
                acc[q][1] = fmaf(w, dx, acc[q][1]);
                acc[q][2] = fmaf(w, dy, acc[q][2]);
                acc[q][3] = fmaf(w * dx, dx, acc[q][3]);
                acc[q][4] = fmaf(w * dx, dy, acc[q][4]);
                acc[q][5] = fmaf(w * dy, dy, acc[q][5]);
            }
        }
    }

    // warp reduce all 24 accumulators
    #pragma unroll
    for (int q = 0; q < 4; q++)
        #pragma unroll
        for (int c = 0; c < 6; c++) {
            float v = acc[q][c];
            #pragma unroll
            for (int o = 16; o; o >>= 1) v += __shfl_xor_sync(0xffffffffu, v, o);
            acc[q][c] = v;
        }
    if ((tid & 31) == 0) {
        const int w = tid >> 5;
        #pragma unroll
        for (int q = 0; q < 4; q++)
            #pragma unroll
            for (int c = 0; c < 6; c++) s_part[w][q * 6 + c] = acc[q][c];
    }
    __syncthreads();

    // 4 parallel fp64 symmetric 3x3 inversions (threads 0..3)
    if (tid < 4) {
        const int q = tid;
        double m[6];
        #pragma unroll
        for (int c = 0; c < 6; c++) {
            float s = 0.f;
            #pragma unroll
            for (int w = 0; w < 8; w++) s += s_part[w][q * 6 + c];
            m[c] = (double)s;
        }
        double a = m[0] + 1e-5, b = m[1], c = m[2];
        double d = m[3] + 1e-5, e = m[4], f = m[5] + 1e-5;
        double c00 = d * f - e * e;
        double c01 = c * e - b * f;
        double c02 = b * e - c * d;
        double det = a * c00 + b * c01 + c * c02;
        double id  = 1.0 / det;
        s_minv[q][0] = (float)(c00 * id);
        s_minv[q][1] = (float)(c01 * id);
        s_minv[q][2] = (float)(c02 * id);
        s_minv[q][3] = (float)((a * f - c * c) * id);
        s_minv[q][4] = (float)((b * c - a * e) * id);
        s_minv[q][5] = (float)((a * d - b * b) * id);
    }
    __syncthreads();

    // ---- Pass 2: outputs ----
    const size_t BN = (size_t)B * (size_t)N;
    #pragma unroll 1
    for (int q = 0; q < 4; q++) {
        const int b = b0 + q;
        if (b >= B) break;
        const float qx = qv[q].x, qy = qv[q].y;
        const float i00 = s_minv[q][0], i01 = s_minv[q][1], i02 = s_minv[q][2];
        const float i11 = s_minv[q][3], i12 = s_minv[q][4], i22 = s_minv[q][5];
        float* __restrict__ o0 = out + (size_t)b * (size_t)N;
        float* __restrict__ o1 = o0 + BN;
        float* __restrict__ o2 = o1 + BN;

        if ((N & 3) == 0) {
            for (int base = tid * 4; base < N; base += 1024) {
                float rp[4], rx[4], ry[4];
                #pragma unroll
                for (int j = 0; j < 4; j++) {
                    const float2 nd = s_nodes[base + j];
                    float dx = qx - nd.x;
                    float dy = qy - nd.y;
                    float d2 = dx * dx + dy * dy + 1e-10f;
                    float w = 0.f;
                    if (d2 <= dil2) {
                        float qq = sqrtf(d2) * inv_dil;
                        w = cubic_w(qq);
                    }
                    rp[j] =  w * (i00 + i01 * dx + i02 * dy);
                    rx[j] = -(w * (i01 + i11 * dx + i12 * dy));
                    ry[j] = -(w * (i02 + i12 * dx + i22 * dy));
                }
                *(float4*)(o0 + base) = make_float4(rp[0], rp[1], rp[2], rp[3]);
                *(float4*)(o1 + base) = make_float4(rx[0], rx[1], rx[2], rx[3]);
                *(float4*)(o2 + base) = make_float4(ry[0], ry[1], ry[2], ry[3]);
            }
        } else {
            for (int n = tid; n < N; n += 256) {
                const float2 nd = s_nodes[n];
                float dx = qx - nd.x;
                float dy = qy - nd.y;
                float d2 = dx * dx + dy * dy + 1e-10f;
                float w = 0.f;
                if (d2 <= dil2) {
                    float qq = sqrtf(d2) * inv_dil;
                    w = cubic_w(qq);
                }
                o0[n] =  w * (i00 + i01 * dx + i02 * dy);
                o1[n] = -(w * (i01 + i11 * dx + i12 * dy));
                o2[n] = -(w * (i02 + i12 * dx + i22 * dy));
            }
        }
    }
}

// ---------------------------------------------------------------------------
// Launch: metadata order is {x, nodes}; output is [3, B, N] fp32.
// ---------------------------------------------------------------------------
extern "C" void kernel_launch(void* const* d_in, const int* in_sizes, int n_in,
                              void* d_out, int out_size) {
    const float2* x     = (const float2*)d_in[0];
    const float2* nodes = (const float2*)d_in[1];
    float* out = (float*)d_out;
    const int B = in_sizes[0] / 2;
    const int N = in_sizes[1] / 2;

    min_dist_kernel<<<(N + 7) / 8, 256>>>(nodes, N);
    dilation_kernel<<<1, 256>>>(N);
    rkpm_kernel<<<(B + 3) / 4, 256>>>(x, nodes, out, B, N);
}

// round 4
// speedup vs baseline: 1.1374x; 1.1374x over previous
#include <cuda_runtime.h>
#include <math.h>

#define NMAX 4096
#define ONE_THIRD2 (2.0f / 3.0f)
#define FOUR_THIRDS (4.0f / 3.0f)

// Scratch (no allocations allowed)
__device__ float g_min_dist[NMAX];

// ---------------------------------------------------------------------------
// Kernel 1: per-node nearest-neighbor distance. One WARP per node i:
// lanes stride the j-range from the smem tile, shuffle-reduce, lane 0 stores.
// No per-i __syncthreads serialization.
// ---------------------------------------------------------------------------
__global__ __launch_bounds__(256) void min_dist_kernel(const float2* __restrict__ nodes, int N) {
    __shared__ float2 s_nodes[NMAX];
    const int tid = threadIdx.x;
    for (int i = tid; i < N; i += 256) s_nodes[i] = nodes[i];
    __syncthreads();

    const int lane = tid & 31;
    const int i = blockIdx.x * 8 + (tid >> 5);
    if (i >= N) return;
    const float2 xi = s_nodes[i];
    float m = 3.4e38f;
    #pragma unroll 4
    for (int j = lane; j < N; j += 32) {
        float dx = xi.x - s_nodes[j].x;
        float dy = xi.y - s_nodes[j].y;
        float d2 = fmaf(dy, dy, dx * dx);
        if (j != i) m = fminf(m, d2);
    }
    #pragma unroll
    for (int o = 16; o; o >>= 1) m = fminf(m, __shfl_xor_sync(0xffffffffu, m, o));
    if (lane == 0) g_min_dist[i] = sqrtf(m);
}

// ---------------------------------------------------------------------------
// Cubic spline weight (matches reference piecewise formula + support mask)
// ---------------------------------------------------------------------------
__device__ __forceinline__ float cubic_w(float q) {
    float w;
    if (q <= 0.5f) w = ONE_THIRD2 + 4.f * q * q * (q - 1.f);
    else           w = FOUR_THIRDS + q * (-4.f + q * (4.f - FOUR_THIRDS * q));
    return (q <= 1.f) ? w : 0.f;
}

// ---------------------------------------------------------------------------
// Kernel 2 (main): each block processes `ngrp` groups of 4 query points
// against one shared-memory node tile. Per block:
//   - stage nodes (once), reduce g_min_dist -> dilation (deterministic, once)
//   - per group: pass 1 moment matrices (registers + shuffle + smem reduce),
//     4 parallel fp64 adjugate inversions, pass 2 streamed float4 outputs.
// Grid sized for a SINGLE wave (<= 6 blocks/SM smem-limited, regs capped 64).
// ---------------------------------------------------------------------------
__global__ __launch_bounds__(256, 4) void rkpm_kernel(const float2* __restrict__ x,
                                                      const float2* __restrict__ nodes,
                                                      float* __restrict__ out,
                                                      int B, int N, int ngrp, int nblocks) {
    __shared__ float2 s_nodes[NMAX];
    __shared__ float  s_red[256];
    __shared__ float  s_part[8][24];
    __shared__ float  s_minv[4][6];
    __shared__ float2 s_q[4];
    __shared__ float  s_params[2];   // inv_dil, dil2

    const int tid = threadIdx.x;
    for (int i = tid; i < N; i += 256) s_nodes[i] = nodes[i];

    // dilation: deterministic per-block tree reduce of g_min_dist (L2-hot)
    {
        float s = 0.f;
        for (int i = tid; i < N; i += 256) s += g_min_dist[i];
        s_red[tid] = s;
        __syncthreads();
        #pragma unroll
        for (int o = 128; o; o >>= 1) {
            if (tid < o) s_red[tid] += s_red[tid + o];
            __syncthreads();
        }
        if (tid == 0) {
            float dil = 2.5f * (s_red[0] / (float)N);
            s_params[0] = 1.f / dil;
            s_params[1] = dil * dil;
        }
        __syncthreads();
    }
    const float inv_dil = s_params[0];
    const float dil2    = s_params[1];
    const size_t BN = (size_t)B * (size_t)N;

    for (int grp = 0; grp < ngrp; grp++) {
        const int b0 = (blockIdx.x + grp * nblocks) * 4;
        if (b0 >= B) break;

        if (tid < 4) {
            int b = b0 + tid;
            s_q[tid] = (b < B) ? x[b] : make_float2(1e10f, 1e10f);
        }
        __syncthreads();

        float2 qv[4];
        #pragma unroll
        for (int q = 0; q < 4; q++) qv[q] = s_q[q];

        float acc[4][6];
        #pragma unroll
        for (int q = 0; q < 4; q++)
            #pragma unroll
            for (int c = 0; c < 6; c++) acc[q][c] = 0.f;

        // ---- Pass 1: moment matrices ----
        for (int n = tid; n < N; n += 256) {
            const float2 nd = s_nodes[n];
            #pragma unroll
            for (int q = 0; q < 4; q++) {
                float dx = qv[q].x - nd.x;
                float dy = qv[q].y - nd.y;
                float d2 = dx * dx + dy * dy + 1e-10f;
                if (d2 <= dil2) {
                    float qq = sqrtf(d2) * inv_dil;
                    float w = cubic_w(qq);
                    acc[q][0] += w;
                    acc[q][1] = fmaf(w, dx, acc[q][1]);
                    acc[q][2] = fmaf(w, dy, acc[q][2]);
                    acc[q][3] = fmaf(w * dx, dx, acc[q][3]);
                    acc[q][4] = fmaf(w * dx, dy, acc[q][4]);
                    acc[q][5] = fmaf(w * dy, dy, acc[q][5]);
                }
            }
        }

        #pragma unroll
        for (int q = 0; q < 4; q++)
            #pragma unroll
            for (int c = 0; c < 6; c++) {
                float v = acc[q][c];
                #pragma unroll
                for (int o = 16; o; o >>= 1) v += __shfl_xor_sync(0xffffffffu, v, o);
                acc[q][c] = v;
            }
        if ((tid & 31) == 0) {
            const int w = tid >> 5;
            #pragma unroll
            for (int q = 0; q < 4; q++)
                #pragma unroll
                for (int c = 0; c < 6; c++) s_part[w][q * 6 + c] = acc[q][c];
        }
        __syncthreads();

        // 4 parallel fp64 symmetric 3x3 adjugate inversions
        if (tid < 4) {
            const int q = tid;
            double m[6];
            #pragma unroll
            for (int c = 0; c < 6; c++) {
                float s = 0.f;
                #pragma unroll
                for (int w = 0; w < 8; w++) s += s_part[w][q * 6 + c];
                m[c] = (double)s;
            }
            double a = m[0] + 1e-5, b = m[1], c = m[2];
            double d = m[3] + 1e-5, e = m[4], f = m[5] + 1e-5;
            double c00 = d * f - e * e;
            double c01 = c * e - b * f;
            double c02 = b * e - c * d;
            double det = a * c00 + b * c01 + c * c02;
            double id  = 1.0 / det;
            s_minv[q][0] = (float)(c00 * id);
            s_minv[q][1] = (float)(c01 * id);
            s_minv[q][2] = (float)(c02 * id);
            s_minv[q][3] = (float)((a * f - c * c) * id);
            s_minv[q][4] = (float)((b * c - a * e) * id);
            s_minv[q][5] = (float)((a * d - b * b) * id);
        }
        __syncthreads();

        // ---- Pass 2: outputs (zero fast path + streaming stores) ----
        #pragma unroll 1
        for (int q = 0; q < 4; q++) {
            const int b = b0 + q;
            if (b >= B) break;
            const float qx = qv[q].x, qy = qv[q].y;
            const float i00 = s_minv[q][0], i01 = s_minv[q][1], i02 = s_minv[q][2];
            const float i11 = s_minv[q][3], i12 = s_minv[q][4], i22 = s_minv[q][5];
            float* __restrict__ o0 = out + (size_t)b * (size_t)N;
            float* __restrict__ o1 = o0 + BN;
            float* __restrict__ o2 = o1 + BN;

            if ((N & 3) == 0) {
                for (int base = tid * 4; base < N; base += 1024) {
                    float rp[4], rx[4], ry[4];
                    #pragma unroll
                    for (int j = 0; j < 4; j++) {
                        const float2 nd = s_nodes[base + j];
                        float dx = qx - nd.x;
                        float dy = qy - nd.y;
                        float d2 = dx * dx + dy * dy + 1e-10f;
                        if (d2 <= dil2) {
                            float w = cubic_w(sqrtf(d2) * inv_dil);
                            rp[j] =  w * (i00 + i01 * dx + i02 * dy);
                            rx[j] = -(w * (i01 + i11 * dx + i12 * dy));
                            ry[j] = -(w * (i02 + i12 * dx + i22 * dy));
                        } else {
                            rp[j] = 0.f; rx[j] = 0.f; ry[j] = 0.f;
                        }
                    }
                    __stcs((float4*)(o0 + base), make_float4(rp[0], rp[1], rp[2], rp[3]));
                    __stcs((float4*)(o1 + base), make_float4(rx[0], rx[1], rx[2], rx[3]));
                    __stcs((float4*)(o2 + base), make_float4(ry[0], ry[1], ry[2], ry[3]));
                }
            } else {
                for (int n = tid; n < N; n += 256) {
                    const float2 nd = s_nodes[n];
                    float dx = qx - nd.x;
                    float dy = qy - nd.y;
                    float d2 = dx * dx + dy * dy + 1e-10f;
                    float w = (d2 <= dil2) ? cubic_w(sqrtf(d2) * inv_dil) : 0.f;
                    o0[n] =  w * (i00 + i01 * dx + i02 * dy);
                    o1[n] = -(w * (i01 + i11 * dx + i12 * dy));
                    o2[n] = -(w * (i02 + i12 * dx + i22 * dy));
                }
            }
        }
        __syncthreads();   // s_q / s_part / s_minv reuse across groups
    }
}

// ---------------------------------------------------------------------------
// Launch: metadata order is {x, nodes}; output is [3, B, N] fp32.
// ---------------------------------------------------------------------------
extern "C" void kernel_launch(void* const* d_in, const int* in_sizes, int n_in,
                              void* d_out, int out_size) {
    const float2* x     = (const float2*)d_in[0];
    const float2* nodes = (const float2*)d_in[1];
    float* out = (float*)d_out;
    const int B = in_sizes[0] / 2;
    const int N = in_sizes[1] / 2;

    min_dist_kernel<<<(N + 7) / 8, 256>>>(nodes, N);

    // Single-wave sizing: 2 groups of 4 queries per block.
    const int groups  = (B + 3) / 4;
    const int ngrp    = 2;
    const int nblocks = (groups + ngrp - 1) / ngrp;
    rkpm_kernel<<<nblocks, 256>>>(x, nodes, out, B, N, ngrp, nblocks);
}